// round 16
// baseline (speedup 1.0000x reference)
#include <cuda_runtime.h>
#include <cuda_fp16.h>

#define NN 100000
#define EE 1600000
#define DIN 128
#define DHID 64
#define DOUT 32
#define SCAN_BLK 1024
#define AGG_BLOCKS 888

// Scratch (allocation-free contract: __device__ globals; zero-init at load,
// g_cnt/g_etotal re-zeroed in k_agg2 so graph replays see the same state)
__device__ int     g_cnt[NN];
__device__ int     g_offs[NN];
__device__ int     g_cursor[NN];
__device__ int     g_etotal;
__device__ float   g_isq[NN];              // (deg+1)^{-1/2}
__device__ int     g_csrc[EE];             // CSR-sorted source BYTE offsets (src*128)
__device__ float   g_h1[NN * DHID];        // gemm1 out (fp32)
__device__ __half2 g_h1h[NN * (DHID / 2)]; // isq-scaled h1 in fp16 (128B rows)
__device__ __half2 g_a1h[NN * (DHID / 2)]; // a1 = relu(...) in fp16 (agg1 out, gemm2 in)
__device__ float   g_h3[NN * DOUT];        // isq-scaled layer-2 features (128B rows)

// ---------------------------------------------------------------- GEMM1 (TF32, smem-staged W)
#define XS_STRIDE 132
#define WS_STRIDE 132
#define SMEM_GEMM1 ((64 * WS_STRIDE + 128 * XS_STRIDE) * 4)

__device__ __forceinline__ unsigned f2tf32(float f) {
    unsigned r;
    asm("cvt.rna.tf32.f32 %0, %1;" : "=r"(r) : "f"(f));
    return r;
}

__device__ __forceinline__ __half2 u2lo(uint2 v) { return *(__half2*)&v.x; }
__device__ __forceinline__ __half2 u2hi(uint2 v) { return *(__half2*)&v.y; }

__global__ __launch_bounds__(256) void k_gemm1(const float* __restrict__ x,
                                               const float* __restrict__ W, int n) {
    extern __shared__ float S[];
    int tid = threadIdx.x;
    unsigned* Ws = (unsigned*)S;           // [64][WS_STRIDE] tf32 bits, Ws[col][k]
    float* Xs = S + 64 * WS_STRIDE;        // [128][XS_STRIDE]
    int warp = tid >> 5;
    int lane = tid & 31;
    int gid = lane >> 2;
    int tig = lane & 3;
    int rb = blockIdx.x * 128;

    // stage W transposed + pre-converted: Ws[col][k] = tf32(W[k*64+col])
    for (int i = tid; i < DIN * DHID; i += 256) {
        int k = i >> 6, col = i & 63;
        Ws[col * WS_STRIDE + k] = f2tf32(__ldg(&W[i]));
    }

    // stage X tile [128 x 128] as float4, zero-fill OOB rows
    {
        float4* Xs4 = (float4*)Xs;
        const float4 zz = make_float4(0.f, 0.f, 0.f, 0.f);
        for (int idx = tid; idx < 128 * 32; idx += 256) {
            int row = idx >> 5, c4 = idx & 31;
            float4 v = (rb + row < n)
                     ? __ldg((const float4*)(x + (size_t)(rb + row) * DIN) + c4)
                     : zz;
            Xs4[row * (XS_STRIDE / 4) + c4] = v;
        }
    }
    __syncthreads();

    int wm = warp * 16;
    float c[8][4];
#pragma unroll
    for (int j = 0; j < 8; j++)
#pragma unroll
        for (int q = 0; q < 4; q++) c[j][q] = 0.f;

#pragma unroll
    for (int ks = 0; ks < 16; ks++) {
        int k = ks * 8;
        unsigned a0 = f2tf32(Xs[(wm + gid) * XS_STRIDE + k + tig]);
        unsigned a1 = f2tf32(Xs[(wm + gid + 8) * XS_STRIDE + k + tig]);
        unsigned a2 = f2tf32(Xs[(wm + gid) * XS_STRIDE + k + tig + 4]);
        unsigned a3 = f2tf32(Xs[(wm + gid + 8) * XS_STRIDE + k + tig + 4]);
#pragma unroll
        for (int j = 0; j < 8; j++) {
            unsigned b0 = Ws[(j * 8 + gid) * WS_STRIDE + k + tig];
            unsigned b1 = Ws[(j * 8 + gid) * WS_STRIDE + k + tig + 4];
            asm volatile(
                "mma.sync.aligned.m16n8k8.row.col.f32.tf32.tf32.f32 "
                "{%0,%1,%2,%3}, {%4,%5,%6,%7}, {%8,%9}, {%0,%1,%2,%3};"
                : "+f"(c[j][0]), "+f"(c[j][1]), "+f"(c[j][2]), "+f"(c[j][3])
                : "r"(a0), "r"(a1), "r"(a2), "r"(a3), "r"(b0), "r"(b1));
        }
    }

    int r0 = rb + wm + gid;
    int r1 = r0 + 8;
#pragma unroll
    for (int j = 0; j < 8; j++) {
        int col = j * 8 + 2 * tig;
        if (r0 < n) *(float2*)&g_h1[(size_t)r0 * DHID + col] = make_float2(c[j][0], c[j][1]);
        if (r1 < n) *(float2*)&g_h1[(size_t)r1 * DHID + col] = make_float2(c[j][2], c[j][3]);
    }
}

// ---------------------------------------------------------------- count: 4 edges/thread (side stream, overlaps gemm1)
__global__ void k_count(const int* __restrict__ dst, int e) {
    int q4 = e >> 2;
    int i = blockIdx.x * 256 + threadIdx.x;
    if (i < q4) {
        int4 d = __ldg((const int4*)dst + i);
        atomicAdd(&g_cnt[d.x], 1);
        atomicAdd(&g_cnt[d.y], 1);
        atomicAdd(&g_cnt[d.z], 1);
        atomicAdd(&g_cnt[d.w], 1);
    } else if (i == q4) {
        for (int idx = q4 << 2; idx < e; idx++)
            atomicAdd(&g_cnt[dst[idx]], 1);
    }
}

// ---------------------------------------------------------------- offsets: shfl warp-scan
__global__ __launch_bounds__(SCAN_BLK) void k_offsets(int n) {
    __shared__ int wsum[32];
    __shared__ int base;
    int i = blockIdx.x * SCAN_BLK + threadIdx.x;
    int lane = threadIdx.x & 31;
    int warp = threadIdx.x >> 5;
    int c = (i < n) ? g_cnt[i] : 0;

    int v = c;
#pragma unroll
    for (int d = 1; d < 32; d <<= 1) {
        int t = __shfl_up_sync(0xffffffff, v, d);
        if (lane >= d) v += t;
    }
    if (lane == 31) wsum[warp] = v;
    __syncthreads();
    if (warp == 0) {
        int s = wsum[lane];
#pragma unroll
        for (int d = 1; d < 32; d <<= 1) {
            int t = __shfl_up_sync(0xffffffff, s, d);
            if (lane >= d) s += t;
        }
        wsum[lane] = s;
        if (lane == 31) base = atomicAdd(&g_etotal, s);
    }
    __syncthreads();
    int pre = (warp > 0 ? wsum[warp - 1] : 0) + v - c;
    if (i < n) {
        int off = base + pre;
        g_offs[i] = off;
        g_cursor[i] = off;
        g_isq[i] = rsqrtf((float)(c + 1));
    }
}

// ---------------------------------------------------------------- fill: 8 edges/thread, BYTE offsets
__global__ void k_fill(const int* __restrict__ src, const int* __restrict__ dst, int e) {
    int q8 = e >> 3;
    int i = blockIdx.x * 256 + threadIdx.x;
    if (i < q8) {
        const int4* s4 = (const int4*)src;
        const int4* d4 = (const int4*)dst;
        int4 sa = __ldg(s4 + 2 * i), sb = __ldg(s4 + 2 * i + 1);
        int4 da = __ldg(d4 + 2 * i), db = __ldg(d4 + 2 * i + 1);
        int p0 = atomicAdd(&g_cursor[da.x], 1);
        int p1 = atomicAdd(&g_cursor[da.y], 1);
        int p2 = atomicAdd(&g_cursor[da.z], 1);
        int p3 = atomicAdd(&g_cursor[da.w], 1);
        int p4 = atomicAdd(&g_cursor[db.x], 1);
        int p5 = atomicAdd(&g_cursor[db.y], 1);
        int p6 = atomicAdd(&g_cursor[db.z], 1);
        int p7 = atomicAdd(&g_cursor[db.w], 1);
        g_csrc[p0] = sa.x << 7; g_csrc[p1] = sa.y << 7;
        g_csrc[p2] = sa.z << 7; g_csrc[p3] = sa.w << 7;
        g_csrc[p4] = sb.x << 7; g_csrc[p5] = sb.y << 7;
        g_csrc[p6] = sb.z << 7; g_csrc[p7] = sb.w << 7;
    } else if (i == q8) {
        for (int idx = q8 << 3; idx < e; idx++) {
            int p = atomicAdd(&g_cursor[dst[idx]], 1);
            g_csrc[p] = src[idx] << 7;
        }
    }
}

// ---------------------------------------------------------------- convert: h1h = fp16(isq * h1)
__global__ void k_convert(int n) {
    int i = blockIdx.x * 256 + threadIdx.x;
    if (i < n * 32) {
        float2 v = ((const float2*)g_h1)[i];
        float s = g_isq[i >> 5];
        g_h1h[i] = __floats2half2_rn(v.x * s, v.y * s);
    }
}

// ---------------------------------------------------------------- agg1: warp-per-node, 2 edges per LDG.64 (proven form)
__global__ __launch_bounds__(256) void k_agg1(const float* __restrict__ b1, int n) {
    int tid = threadIdx.x;
    int lane = tid & 31;
    int ws = tid >> 5;
    int hl = lane & 15;
    int grp = lane >> 4;
    int nwarps = gridDim.x * 8;
    const char* hb = (const char*)g_h1h;
    float4 b = __ldg((const float4*)b1 + hl);  // dims 4hl..4hl+3

    for (int w = blockIdx.x * 8 + ws; w < n; w += nwarps) {
        int beg = g_offs[w];
        int deg = g_cnt[w];
        float isqd = g_isq[w];

        float a0 = 0.f, a1v = 0.f, a2 = 0.f, a3 = 0.f;

        // self term (group 0 only)
        {
            uint2 u = __ldg((const uint2*)(hb + ((size_t)w << 7)) + hl);
            if (!grp) {
                float2 f0 = __half22float2(u2lo(u));
                float2 f1 = __half22float2(u2hi(u));
                a0 += f0.x; a1v += f0.y; a2 += f1.x; a3 += f1.y;
            }
        }

        int done = 0;
        while (done < deg) {
            int m = deg - done; if (m > 32) m = 32;
            int sid = (lane < m) ? __ldg(&g_csrc[beg + done + lane]) : 0;
            int j = 0;
            for (; j + 8 <= m; j += 8) {  // 4 LDGs = 8 edges
                uint2 u[4];
#pragma unroll
                for (int t = 0; t < 4; t++) {
                    int s = __shfl_sync(0xffffffffu, sid, j + 2 * t + grp);
                    u[t] = __ldg((const uint2*)(hb + s) + hl);
                }
#pragma unroll
                for (int t = 0; t < 4; t++) {
                    float2 f0 = __half22float2(u2lo(u[t]));
                    float2 f1 = __half22float2(u2hi(u[t]));
                    a0 += f0.x; a1v += f0.y; a2 += f1.x; a3 += f1.y;
                }
            }
            for (; j < m; j += 2) {  // pair tail; odd last edge handled by group 0 only
                bool lastodd = (j + 1 >= m);
                int slot = j + grp; if (slot >= m) slot = j;
                int s = __shfl_sync(0xffffffffu, sid, slot);
                uint2 u = __ldg((const uint2*)(hb + s) + hl);
                if (!(lastodd && grp)) {
                    float2 f0 = __half22float2(u2lo(u));
                    float2 f1 = __half22float2(u2hi(u));
                    a0 += f0.x; a1v += f0.y; a2 += f1.x; a3 += f1.y;
                }
            }
            done += m;
        }

        a0  += __shfl_xor_sync(0xffffffffu, a0, 16);
        a1v += __shfl_xor_sync(0xffffffffu, a1v, 16);
        a2  += __shfl_xor_sync(0xffffffffu, a2, 16);
        a3  += __shfl_xor_sync(0xffffffffu, a3, 16);

        if (!grp) {
            float r0 = fmaxf(fmaf(a0,  isqd, b.x), 0.f);
            float r1 = fmaxf(fmaf(a1v, isqd, b.y), 0.f);
            float r2 = fmaxf(fmaf(a2,  isqd, b.z), 0.f);
            float r3 = fmaxf(fmaf(a3,  isqd, b.w), 0.f);
            uint2 o;
            *(__half2*)&o.x = __floats2half2_rn(r0, r1);
            *(__half2*)&o.y = __floats2half2_rn(r2, r3);
            ((uint2*)((char*)g_a1h + ((size_t)w << 7)))[hl] = o;
        }
    }
}

// ---------------------------------------------------------------- GEMM2: h3' = isq * (a1 @ W2)  [N,64]x[64,32], fp16 input
__global__ __launch_bounds__(256) void k_gemm2(const float* __restrict__ W, int n) {
    __shared__ float Xs[64][DHID];  // 16 KB
    int tid = threadIdx.x;
    int rb = blockIdx.x * 64;
    int rows = n - rb; if (rows > 64) rows = 64;

    const __half2* a2 = g_a1h + (size_t)rb * 32;
    for (int i = tid; i < rows * 32; i += 256) {
        float2 f = __half22float2(a2[i]);
        int row = i >> 5, slot = i & 31;
        Xs[row][2 * slot] = f.x;
        Xs[row][2 * slot + 1] = f.y;
    }
    __syncthreads();

    int colq = tid & 7;
    int rowq = tid >> 3;
    float acc[2][4] = {};
    const float4* W4 = (const float4*)W;

#pragma unroll 8
    for (int k = 0; k < DHID; k += 4) {
        float4 xr[2];
#pragma unroll
        for (int i = 0; i < 2; i++)
            xr[i] = *(const float4*)&Xs[rowq * 2 + i][k];
#pragma unroll
        for (int kk = 0; kk < 4; kk++) {
            float4 w = __ldg(&W4[(k + kk) * 8 + colq]);
#pragma unroll
            for (int i = 0; i < 2; i++) {
                float xv = ((const float*)&xr[i])[kk];
                acc[i][0] = fmaf(xv, w.x, acc[i][0]);
                acc[i][1] = fmaf(xv, w.y, acc[i][1]);
                acc[i][2] = fmaf(xv, w.z, acc[i][2]);
                acc[i][3] = fmaf(xv, w.w, acc[i][3]);
            }
        }
    }
#pragma unroll
    for (int i = 0; i < 2; i++) {
        int r = rb + rowq * 2 + i;
        if (r < n) {
            float s = g_isq[r];
            float4 v = make_float4(s * acc[i][0], s * acc[i][1],
                                   s * acc[i][2], s * acc[i][3]);
            *(float4*)&g_h3[(size_t)r * DOUT + colq * 4] = v;  // pre-scaled h3'
        }
    }
}

// ---------------------------------------------------------------- agg2: warp-per-node, 2 edges per LDG.64 (+ state reset)
__global__ __launch_bounds__(256) void k_agg2(float* __restrict__ out,
                                              const float* __restrict__ b2, int n) {
    int tid = threadIdx.x;
    int lane = tid & 31;
    int ws = tid >> 5;
    int hl = lane & 15;
    int grp = lane >> 4;
    int nwarps = gridDim.x * 8;
    const char* hb = (const char*)g_h3;
    float2 bb = __ldg((const float2*)b2 + hl);  // dims 2hl, 2hl+1
    if (blockIdx.x == 0 && tid == 0) g_etotal = 0;

    for (int w = blockIdx.x * 8 + ws; w < n; w += nwarps) {
        int beg = g_offs[w];
        int deg = g_cnt[w];
        float isqd = g_isq[w];

        float ax = 0.f, ay = 0.f;

        {
            float2 u = __ldg((const float2*)(hb + ((size_t)w << 7)) + hl);
            if (!grp) { ax += u.x; ay += u.y; }
        }

        int done = 0;
        while (done < deg) {
            int m = deg - done; if (m > 32) m = 32;
            int sid = (lane < m) ? __ldg(&g_csrc[beg + done + lane]) : 0;
            int j = 0;
            for (; j + 8 <= m; j += 8) {
                float2 u[4];
#pragma unroll
                for (int t = 0; t < 4; t++) {
                    int s = __shfl_sync(0xffffffffu, sid, j + 2 * t + grp);
                    u[t] = __ldg((const float2*)(hb + s) + hl);
                }
#pragma unroll
                for (int t = 0; t < 4; t++) { ax += u[t].x; ay += u[t].y; }
            }
            for (; j < m; j += 2) {
                bool lastodd = (j + 1 >= m);
                int slot = j + grp; if (slot >= m) slot = j;
                int s = __shfl_sync(0xffffffffu, sid, slot);
                float2 u = __ldg((const float2*)(hb + s) + hl);
                if (!(lastodd && grp)) { ax += u.x; ay += u.y; }
            }
            done += m;
        }

        ax += __shfl_xor_sync(0xffffffffu, ax, 16);
        ay += __shfl_xor_sync(0xffffffffu, ay, 16);

        if (!grp) {
            float2 o;
            o.x = fmaf(ax, isqd, bb.x);
            o.y = fmaf(ay, isqd, bb.y);
            ((float2*)((char*)out + ((size_t)w << 7)))[hl] = o;
        }

        if (lane == 0) g_cnt[w] = 0;  // reset for next graph replay
    }
}

// ----------------------------------------------------------------
extern "C" void kernel_launch(void* const* d_in, const int* in_sizes, int n_in,
                              void* d_out, int out_size) {
    const float* x  = (const float*)d_in[0];
    const int*   ei = (const int*)d_in[1];
    const float* W1 = (const float*)d_in[2];
    const float* b1 = (const float*)d_in[3];
    const float* W2 = (const float*)d_in[4];
    const float* b2 = (const float*)d_in[5];
    float* out = (float*)d_out;

    int n = in_sizes[0] / DIN;
    int e = in_sizes[1] / 2;
    const int* src = ei;
    const int* dst = ei + e;

    // one-time host-side infra (created on the pre-capture correctness call;
    // no device memory involved)
    static cudaStream_t s_side = nullptr;
    static cudaEvent_t ev_root = nullptr, ev_join = nullptr;
    if (!s_side) {
        cudaStreamCreateWithFlags(&s_side, cudaStreamNonBlocking);
        cudaEventCreateWithFlags(&ev_root, cudaEventDisableTiming);
        cudaEventCreateWithFlags(&ev_join, cudaEventDisableTiming);
    }

    // fork: side stream joins the capture via the root event
    cudaEventRecord(ev_root, 0);
    cudaStreamWaitEvent(s_side, ev_root, 0);

    // branch A (side stream): edge indexing — count -> offsets -> fill
    {
        int ncnt = ((e >> 2) + 1 + 255) / 256;
        k_count<<<ncnt, 256, 0, s_side>>>(dst, e);
        k_offsets<<<(n + SCAN_BLK - 1) / SCAN_BLK, SCAN_BLK, 0, s_side>>>(n);
        int nfb = ((e >> 3) + 1 + 255) / 256;
        k_fill<<<nfb, 256, 0, s_side>>>(src, dst, e);
        cudaEventRecord(ev_join, s_side);
    }

    // branch B (main stream): gemm1
    {
        cudaFuncSetAttribute(k_gemm1, cudaFuncAttributeMaxDynamicSharedMemorySize,
                             SMEM_GEMM1);
        k_gemm1<<<(n + 127) / 128, 256, SMEM_GEMM1>>>(x, W1, n);
    }

    // join, then the dependent chain on the main stream
    cudaStreamWaitEvent(0, ev_join, 0);
    k_convert<<<(n * 32 + 255) / 256, 256>>>(n);
    k_agg1<<<AGG_BLOCKS, 256>>>(b1, n);
    k_gemm2<<<(n + 63) / 64, 256>>>(W2, n);
    k_agg2<<<AGG_BLOCKS, 256>>>(out, b2, n);
}

// round 17
// speedup vs baseline: 1.1691x; 1.1691x over previous
#include <cuda_runtime.h>
#include <cuda_fp16.h>

#define NN 100000
#define EE 1600000
#define DIN 128
#define DHID 64
#define DOUT 32
#define SCAN_BLK 1024
#define AGG_BLOCKS 888
#define CNT_BLOCKS 148

// Scratch (allocation-free contract: __device__ globals; zero-init at load,
// g_cnt/g_etotal re-zeroed in k_agg2 so graph replays see the same state)
__device__ int     g_cnt[NN];
__device__ int     g_offs[NN];
__device__ int     g_cursor[NN];
__device__ int     g_etotal;
__device__ float   g_isq[NN];              // (deg+1)^{-1/2}
__device__ int     g_csrc[EE];             // CSR-sorted source BYTE offsets (src*128)
__device__ float   g_h1[NN * DHID];        // gemm1 out (fp32)
__device__ __half2 g_h1h[NN * (DHID / 2)]; // isq-scaled h1 in fp16 (128B rows)
__device__ __half2 g_a1h[NN * (DHID / 2)]; // a1 = relu(...) in fp16 (agg1 out, gemm2 in)
__device__ float   g_h3[NN * DOUT];        // isq-scaled layer-2 features (128B rows)

// ---------------------------------------------------------------- GEMM1 (fp16 m16n8k16 MMA) + specialized count blocks
// smem (u32 view): Ws [64][68] (fp16 pairs, W transposed) then Xs [128][68]
#define WROW_U32 68
#define SMEM_GEMM1 ((64 * WROW_U32 + 128 * WROW_U32) * 4)  // 52224 B

__device__ __forceinline__ __half2 u2lo(uint2 v) { return *(__half2*)&v.x; }
__device__ __forceinline__ __half2 u2hi(uint2 v) { return *(__half2*)&v.y; }

__global__ __launch_bounds__(256) void k_gemm1_count(const float* __restrict__ x,
                                                     const float* __restrict__ W,
                                                     const int* __restrict__ dst,
                                                     int e, int n) {
    extern __shared__ unsigned S[];
    int tid = threadIdx.x;

    // ---- count-only blocks (scheduled first, retire early, overlap with gemm)
    if ((int)blockIdx.x < CNT_BLOCKS) {
        int q4 = e >> 2;
        int stride = CNT_BLOCKS * 256;
        for (int i = blockIdx.x * 256 + tid; i < q4; i += stride) {
            int4 d = __ldg((const int4*)dst + i);
            atomicAdd(&g_cnt[d.x], 1);
            atomicAdd(&g_cnt[d.y], 1);
            atomicAdd(&g_cnt[d.z], 1);
            atomicAdd(&g_cnt[d.w], 1);
        }
        if (blockIdx.x == 0 && tid == 0)
            for (int idx = q4 << 2; idx < e; idx++)
                atomicAdd(&g_cnt[dst[idx]], 1);
        return;
    }

    // ---- gemm blocks
    int gb = blockIdx.x - CNT_BLOCKS;
    unsigned* Ws = S;                    // [64][WROW_U32] fp16-pair rows, Ws[col][k/2]
    unsigned* Xs = S + 64 * WROW_U32;    // [128][WROW_U32]
    __half* Wsh = (__half*)Ws;           // half view for staging (stride 136)
    int warp = tid >> 5;
    int lane = tid & 31;
    int gid = lane >> 2;
    int tig = lane & 3;
    int rb = gb * 128;

    // stage W transposed + fp16: Wsh[col*136 + k] = (half)W[k*64+col]  (coalesced LDG)
    for (int i = tid; i < DIN * DHID; i += 256) {
        int k = i >> 6, col = i & 63;
        Wsh[col * 136 + k] = __float2half(__ldg(&W[i]));
    }

    // stage X tile [128 x 128] as fp16 pairs, zero-fill OOB rows
    {
        const float4 zz = make_float4(0.f, 0.f, 0.f, 0.f);
        for (int idx = tid; idx < 128 * 32; idx += 256) {
            int row = idx >> 5, c4 = idx & 31;
            float4 v = (rb + row < n)
                     ? __ldg((const float4*)(x + (size_t)(rb + row) * DIN) + c4)
                     : zz;
            __half2 h0 = __floats2half2_rn(v.x, v.y);
            __half2 h1 = __floats2half2_rn(v.z, v.w);
            Xs[row * WROW_U32 + 2 * c4]     = *(unsigned*)&h0;
            Xs[row * WROW_U32 + 2 * c4 + 1] = *(unsigned*)&h1;
        }
    }
    __syncthreads();

    int wm = warp * 16;
    float c[8][4];
#pragma unroll
    for (int j = 0; j < 8; j++)
#pragma unroll
        for (int q = 0; q < 4; q++) c[j][q] = 0.f;

#pragma unroll
    for (int ks = 0; ks < 8; ks++) {      // K=128, 16 per mma
        int kq = ks * 8;                  // u32 offset within row (k/2)
        // A fragment (bank = (4*row+tig)%32, conflict-free)
        unsigned a0 = Xs[(wm + gid) * WROW_U32 + kq + tig];
        unsigned a1 = Xs[(wm + gid + 8) * WROW_U32 + kq + tig];
        unsigned a2 = Xs[(wm + gid) * WROW_U32 + kq + tig + 4];
        unsigned a3 = Xs[(wm + gid + 8) * WROW_U32 + kq + tig + 4];
#pragma unroll
        for (int j = 0; j < 8; j++) {
            unsigned b0 = Ws[(j * 8 + gid) * WROW_U32 + kq + tig];
            unsigned b1 = Ws[(j * 8 + gid) * WROW_U32 + kq + tig + 4];
            asm volatile(
                "mma.sync.aligned.m16n8k16.row.col.f32.f16.f16.f32 "
                "{%0,%1,%2,%3}, {%4,%5,%6,%7}, {%8,%9}, {%0,%1,%2,%3};"
                : "+f"(c[j][0]), "+f"(c[j][1]), "+f"(c[j][2]), "+f"(c[j][3])
                : "r"(a0), "r"(a1), "r"(a2), "r"(a3), "r"(b0), "r"(b1));
        }
    }

    int r0 = rb + wm + gid;
    int r1 = r0 + 8;
#pragma unroll
    for (int j = 0; j < 8; j++) {
        int col = j * 8 + 2 * tig;
        if (r0 < n) *(float2*)&g_h1[(size_t)r0 * DHID + col] = make_float2(c[j][0], c[j][1]);
        if (r1 < n) *(float2*)&g_h1[(size_t)r1 * DHID + col] = make_float2(c[j][2], c[j][3]);
    }
}

// ---------------------------------------------------------------- offsets: shfl warp-scan
__global__ __launch_bounds__(SCAN_BLK) void k_offsets(int n) {
    __shared__ int wsum[32];
    __shared__ int base;
    int i = blockIdx.x * SCAN_BLK + threadIdx.x;
    int lane = threadIdx.x & 31;
    int warp = threadIdx.x >> 5;
    int c = (i < n) ? g_cnt[i] : 0;

    int v = c;
#pragma unroll
    for (int d = 1; d < 32; d <<= 1) {
        int t = __shfl_up_sync(0xffffffff, v, d);
        if (lane >= d) v += t;
    }
    if (lane == 31) wsum[warp] = v;
    __syncthreads();
    if (warp == 0) {
        int s = wsum[lane];
#pragma unroll
        for (int d = 1; d < 32; d <<= 1) {
            int t = __shfl_up_sync(0xffffffff, s, d);
            if (lane >= d) s += t;
        }
        wsum[lane] = s;
        if (lane == 31) base = atomicAdd(&g_etotal, s);
    }
    __syncthreads();
    int pre = (warp > 0 ? wsum[warp - 1] : 0) + v - c;
    if (i < n) {
        int off = base + pre;
        g_offs[i] = off;
        g_cursor[i] = off;
        g_isq[i] = rsqrtf((float)(c + 1));
    }
}

// ---------------------------------------------------------------- fused: CSR fill (8 edges/thread, BYTE offsets) + h1 scale/convert
__global__ void k_fill_convert(const int* __restrict__ src, const int* __restrict__ dst,
                               int e, int n, int nfb) {
    if ((int)blockIdx.x < nfb) {
        int q8 = e >> 3;
        int i = blockIdx.x * 256 + threadIdx.x;
        if (i < q8) {
            const int4* s4 = (const int4*)src;
            const int4* d4 = (const int4*)dst;
            int4 sa = __ldg(s4 + 2 * i), sb = __ldg(s4 + 2 * i + 1);
            int4 da = __ldg(d4 + 2 * i), db = __ldg(d4 + 2 * i + 1);
            int p0 = atomicAdd(&g_cursor[da.x], 1);
            int p1 = atomicAdd(&g_cursor[da.y], 1);
            int p2 = atomicAdd(&g_cursor[da.z], 1);
            int p3 = atomicAdd(&g_cursor[da.w], 1);
            int p4 = atomicAdd(&g_cursor[db.x], 1);
            int p5 = atomicAdd(&g_cursor[db.y], 1);
            int p6 = atomicAdd(&g_cursor[db.z], 1);
            int p7 = atomicAdd(&g_cursor[db.w], 1);
            g_csrc[p0] = sa.x << 7; g_csrc[p1] = sa.y << 7;
            g_csrc[p2] = sa.z << 7; g_csrc[p3] = sa.w << 7;
            g_csrc[p4] = sb.x << 7; g_csrc[p5] = sb.y << 7;
            g_csrc[p6] = sb.z << 7; g_csrc[p7] = sb.w << 7;
        } else if (i == q8) {
            for (int idx = q8 << 3; idx < e; idx++) {
                int p = atomicAdd(&g_cursor[dst[idx]], 1);
                g_csrc[p] = src[idx] << 7;
            }
        }
    } else {
        int i = (blockIdx.x - nfb) * 256 + threadIdx.x;
        if (i < n * 32) {
            float2 v = ((const float2*)g_h1)[i];
            float s = g_isq[i >> 5];
            g_h1h[i] = __floats2half2_rn(v.x * s, v.y * s);
        }
    }
}

// ---------------------------------------------------------------- agg1: warp-per-node, 2 edges per LDG.64 (proven form)
__global__ __launch_bounds__(256) void k_agg1(const float* __restrict__ b1, int n) {
    int tid = threadIdx.x;
    int lane = tid & 31;
    int ws = tid >> 5;
    int hl = lane & 15;
    int grp = lane >> 4;
    int nwarps = gridDim.x * 8;
    const char* hb = (const char*)g_h1h;
    float4 b = __ldg((const float4*)b1 + hl);  // dims 4hl..4hl+3

    for (int w = blockIdx.x * 8 + ws; w < n; w += nwarps) {
        int beg = g_offs[w];
        int deg = g_cnt[w];
        float isqd = g_isq[w];

        float a0 = 0.f, a1v = 0.f, a2 = 0.f, a3 = 0.f;

        // self term (group 0 only)
        {
            uint2 u = __ldg((const uint2*)(hb + ((size_t)w << 7)) + hl);
            if (!grp) {
                float2 f0 = __half22float2(u2lo(u));
                float2 f1 = __half22float2(u2hi(u));
                a0 += f0.x; a1v += f0.y; a2 += f1.x; a3 += f1.y;
            }
        }

        int done = 0;
        while (done < deg) {
            int m = deg - done; if (m > 32) m = 32;
            int sid = (lane < m) ? __ldg(&g_csrc[beg + done + lane]) : 0;
            int j = 0;
            for (; j + 8 <= m; j += 8) {  // 4 LDGs = 8 edges
                uint2 u[4];
#pragma unroll
                for (int t = 0; t < 4; t++) {
                    int s = __shfl_sync(0xffffffffu, sid, j + 2 * t + grp);
                    u[t] = __ldg((const uint2*)(hb + s) + hl);
                }
#pragma unroll
                for (int t = 0; t < 4; t++) {
                    float2 f0 = __half22float2(u2lo(u[t]));
                    float2 f1 = __half22float2(u2hi(u[t]));
                    a0 += f0.x; a1v += f0.y; a2 += f1.x; a3 += f1.y;
                }
            }
            for (; j < m; j += 2) {  // pair tail; odd last edge handled by group 0 only
                bool lastodd = (j + 1 >= m);
                int slot = j + grp; if (slot >= m) slot = j;
                int s = __shfl_sync(0xffffffffu, sid, slot);
                uint2 u = __ldg((const uint2*)(hb + s) + hl);
                if (!(lastodd && grp)) {
                    float2 f0 = __half22float2(u2lo(u));
                    float2 f1 = __half22float2(u2hi(u));
                    a0 += f0.x; a1v += f0.y; a2 += f1.x; a3 += f1.y;
                }
            }
            done += m;
        }

        a0  += __shfl_xor_sync(0xffffffffu, a0, 16);
        a1v += __shfl_xor_sync(0xffffffffu, a1v, 16);
        a2  += __shfl_xor_sync(0xffffffffu, a2, 16);
        a3  += __shfl_xor_sync(0xffffffffu, a3, 16);

        if (!grp) {
            float r0 = fmaxf(fmaf(a0,  isqd, b.x), 0.f);
            float r1 = fmaxf(fmaf(a1v, isqd, b.y), 0.f);
            float r2 = fmaxf(fmaf(a2,  isqd, b.z), 0.f);
            float r3 = fmaxf(fmaf(a3,  isqd, b.w), 0.f);
            uint2 o;
            *(__half2*)&o.x = __floats2half2_rn(r0, r1);
            *(__half2*)&o.y = __floats2half2_rn(r2, r3);
            ((uint2*)((char*)g_a1h + ((size_t)w << 7)))[hl] = o;
        }
    }
}

// ---------------------------------------------------------------- GEMM2: h3' = isq * (a1 @ W2)  [N,64]x[64,32], fp16 input
__global__ __launch_bounds__(256) void k_gemm2(const float* __restrict__ W, int n) {
    __shared__ float Xs[64][DHID];  // 16 KB
    int tid = threadIdx.x;
    int rb = blockIdx.x * 64;
    int rows = n - rb; if (rows > 64) rows = 64;

    const __half2* a2 = g_a1h + (size_t)rb * 32;
    for (int i = tid; i < rows * 32; i += 256) {
        float2 f = __half22float2(a2[i]);
        int row = i >> 5, slot = i & 31;
        Xs[row][2 * slot] = f.x;
        Xs[row][2 * slot + 1] = f.y;
    }
    __syncthreads();

    int colq = tid & 7;
    int rowq = tid >> 3;
    float acc[2][4] = {};
    const float4* W4 = (const float4*)W;

#pragma unroll 8
    for (int k = 0; k < DHID; k += 4) {
        float4 xr[2];
#pragma unroll
        for (int i = 0; i < 2; i++)
            xr[i] = *(const float4*)&Xs[rowq * 2 + i][k];
#pragma unroll
        for (int kk = 0; kk < 4; kk++) {
            float4 w = __ldg(&W4[(k + kk) * 8 + colq]);
#pragma unroll
            for (int i = 0; i < 2; i++) {
                float xv = ((const float*)&xr[i])[kk];
                acc[i][0] = fmaf(xv, w.x, acc[i][0]);
                acc[i][1] = fmaf(xv, w.y, acc[i][1]);
                acc[i][2] = fmaf(xv, w.z, acc[i][2]);
                acc[i][3] = fmaf(xv, w.w, acc[i][3]);
            }
        }
    }
#pragma unroll
    for (int i = 0; i < 2; i++) {
        int r = rb + rowq * 2 + i;
        if (r < n) {
            float s = g_isq[r];
            float4 v = make_float4(s * acc[i][0], s * acc[i][1],
                                   s * acc[i][2], s * acc[i][3]);
            *(float4*)&g_h3[(size_t)r * DOUT + colq * 4] = v;  // pre-scaled h3'
        }
    }
}

// ---------------------------------------------------------------- agg2: warp-per-node, 2 edges per LDG.64 (+ state reset)
__global__ __launch_bounds__(256) void k_agg2(float* __restrict__ out,
                                              const float* __restrict__ b2, int n) {
    int tid = threadIdx.x;
    int lane = tid & 31;
    int ws = tid >> 5;
    int hl = lane & 15;
    int grp = lane >> 4;
    int nwarps = gridDim.x * 8;
    const char* hb = (const char*)g_h3;
    float2 bb = __ldg((const float2*)b2 + hl);  // dims 2hl, 2hl+1
    if (blockIdx.x == 0 && tid == 0) g_etotal = 0;

    for (int w = blockIdx.x * 8 + ws; w < n; w += nwarps) {
        int beg = g_offs[w];
        int deg = g_cnt[w];
        float isqd = g_isq[w];

        float ax = 0.f, ay = 0.f;

        {
            float2 u = __ldg((const float2*)(hb + ((size_t)w << 7)) + hl);
            if (!grp) { ax += u.x; ay += u.y; }
        }

        int done = 0;
        while (done < deg) {
            int m = deg - done; if (m > 32) m = 32;
            int sid = (lane < m) ? __ldg(&g_csrc[beg + done + lane]) : 0;
            int j = 0;
            for (; j + 8 <= m; j += 8) {
                float2 u[4];
#pragma unroll
                for (int t = 0; t < 4; t++) {
                    int s = __shfl_sync(0xffffffffu, sid, j + 2 * t + grp);
                    u[t] = __ldg((const float2*)(hb + s) + hl);
                }
#pragma unroll
                for (int t = 0; t < 4; t++) { ax += u[t].x; ay += u[t].y; }
            }
            for (; j < m; j += 2) {
                bool lastodd = (j + 1 >= m);
                int slot = j + grp; if (slot >= m) slot = j;
                int s = __shfl_sync(0xffffffffu, sid, slot);
                float2 u = __ldg((const float2*)(hb + s) + hl);
                if (!(lastodd && grp)) { ax += u.x; ay += u.y; }
            }
            done += m;
        }

        ax += __shfl_xor_sync(0xffffffffu, ax, 16);
        ay += __shfl_xor_sync(0xffffffffu, ay, 16);

        if (!grp) {
            float2 o;
            o.x = fmaf(ax, isqd, bb.x);
            o.y = fmaf(ay, isqd, bb.y);
            ((float2*)((char*)out + ((size_t)w << 7)))[hl] = o;
        }

        if (lane == 0) g_cnt[w] = 0;  // reset for next graph replay
    }
}

// ----------------------------------------------------------------
extern "C" void kernel_launch(void* const* d_in, const int* in_sizes, int n_in,
                              void* d_out, int out_size) {
    const float* x  = (const float*)d_in[0];
    const int*   ei = (const int*)d_in[1];
    const float* W1 = (const float*)d_in[2];
    const float* b1 = (const float*)d_in[3];
    const float* W2 = (const float*)d_in[4];
    const float* b2 = (const float*)d_in[5];
    float* out = (float*)d_out;

    int n = in_sizes[0] / DIN;
    int e = in_sizes[1] / 2;
    const int* src = ei;
    const int* dst = ei + e;

    {
        int ngemm = (n + 127) / 128;
        cudaFuncSetAttribute(k_gemm1_count, cudaFuncAttributeMaxDynamicSharedMemorySize,
                             SMEM_GEMM1);
        k_gemm1_count<<<CNT_BLOCKS + ngemm, 256, SMEM_GEMM1>>>(x, W1, dst, e, n);
    }
    k_offsets<<<(n + SCAN_BLK - 1) / SCAN_BLK, SCAN_BLK>>>(n);
    {
        int nfb = ((e >> 3) + 1 + 255) / 256;
        int ncb = (n * 32 + 255) / 256;
        k_fill_convert<<<nfb + ncb, 256>>>(src, dst, e, n, nfb);
    }

    k_agg1<<<AGG_BLOCKS, 256>>>(b1, n);
    k_gemm2<<<(n + 63) / 64, 256>>>(W2, n);
    k_agg2<<<AGG_BLOCKS, 256>>>(out, b2, n);
}